// round 16
// baseline (speedup 1.0000x reference)
#include <cuda_runtime.h>
#include <cuda_bf16.h>
#include <cstdint>
#include <math.h>

#define BATCH 16
#define NSEQ  1024
#define NH    8
#define HD    64
#define DM    512
#define EXC   0.18033688011112042f   // 0.125 * log2(e), folded into Q

// ---------------- scratch (static device arrays; no allocation) ----------------
#define QKV_ELEMS (BATCH*NH*NSEQ*HD)
__device__ __nv_bfloat16 g_qhi[QKV_ELEMS];
__device__ __nv_bfloat16 g_qlo[QKV_ELEMS];
__device__ __nv_bfloat16 g_khi[QKV_ELEMS];
__device__ __nv_bfloat16 g_klo[QKV_ELEMS];
__device__ __nv_bfloat16 g_vhi[QKV_ELEMS];
__device__ __nv_bfloat16 g_vlo[QKV_ELEMS];
__device__ float g_attn[BATCH*NSEQ*DM];
#define WMAT (512*512)
__device__ __nv_bfloat16 g_whi[4*WMAT];
__device__ __nv_bfloat16 g_wlo[4*WMAT];

// =============================================================================
// helpers
// =============================================================================
__device__ __forceinline__ uint32_t smem_u32(const void* p) {
    uint32_t a;
    asm("{ .reg .u64 t; cvta.to.shared.u64 t, %1; cvt.u32.u64 %0, t; }"
        : "=r"(a) : "l"(p));
    return a;
}
__device__ __forceinline__ void ldsm_x4(uint32_t* r, uint32_t addr) {
    asm volatile("ldmatrix.sync.aligned.m8n8.x4.shared.b16 {%0,%1,%2,%3}, [%4];"
        : "=r"(r[0]), "=r"(r[1]), "=r"(r[2]), "=r"(r[3]) : "r"(addr));
}
__device__ __forceinline__ void ldsm_x4t(uint32_t* r, uint32_t addr) {
    asm volatile("ldmatrix.sync.aligned.m8n8.x4.trans.shared.b16 {%0,%1,%2,%3}, [%4];"
        : "=r"(r[0]), "=r"(r[1]), "=r"(r[2]), "=r"(r[3]) : "r"(addr));
}
__device__ __forceinline__ void mma_bf16(float* c, const uint32_t* a,
                                         uint32_t b0, uint32_t b1) {
    asm volatile(
        "mma.sync.aligned.m16n8k16.row.col.f32.bf16.bf16.f32 "
        "{%0,%1,%2,%3}, {%4,%5,%6,%7}, {%8,%9}, {%0,%1,%2,%3};"
        : "+f"(c[0]), "+f"(c[1]), "+f"(c[2]), "+f"(c[3])
        : "r"(a[0]), "r"(a[1]), "r"(a[2]), "r"(a[3]), "r"(b0), "r"(b1));
}
__device__ __forceinline__ void cp16(uint32_t dst, const void* src) {
    asm volatile("cp.async.cg.shared.global [%0], [%1], 16;" :: "r"(dst), "l"(src));
}
#define CP_COMMIT() asm volatile("cp.async.commit_group;" ::: "memory")
#define CP_WAIT0()  asm volatile("cp.async.wait_group 0;" ::: "memory")
#define CP_WAIT1()  asm volatile("cp.async.wait_group 1;" ::: "memory")

// Truncation-based hi/lo split of a pair (a,b):
//   hi-word = {bf16_trunc(b) : bf16_trunc(a)}  (a in low 16)
//   lo-word = {bf16_trunc(rb) : bf16_trunc(ra)}, ra = a - hi(a) EXACT in fp32
// 3 ops per output word vs ~6 for RN converts; split-3 reconstruction error
// grows only in the dropped lo*lo term (2^-16 rel).
__device__ __forceinline__ void pack_trunc2(float a, float b,
                                            uint32_t& hi, uint32_t& lo) {
    uint32_t au = __float_as_uint(a), bu = __float_as_uint(b);
    uint32_t ah = au & 0xFFFF0000u, bh = bu & 0xFFFF0000u;
    float ra = a - __uint_as_float(ah);
    float rb = b - __uint_as_float(bh);
    hi = __byte_perm(ah, bh, 0x7632);
    lo = __byte_perm(__float_as_uint(ra), __float_as_uint(rb), 0x7632);
}
// word: low16 = bf16_trunc(p), high16 = bf16_trunc(p - hi)
__device__ __forceinline__ uint32_t packP(float p) {
    uint32_t pu = __float_as_uint(p);
    uint32_t ph = pu & 0xFFFF0000u;
    float r = p - __uint_as_float(ph);
    return __byte_perm(ph, __float_as_uint(r), 0x7632);
}

// =============================================================================
// Weight pre-conversion: fp32 [512,512] -> bf16 hi/lo planes (once, all 4 mats)
// =============================================================================
__global__ __launch_bounds__(256) void conv_w(
    const float* w0, const float* w1, const float* w2, const float* w3,
    __nv_bfloat16* hi, __nv_bfloat16* lo)
{
    const int m = blockIdx.y;
    const float* w = (m == 0) ? w0 : (m == 1) ? w1 : (m == 2) ? w2 : w3;
    int idx = (blockIdx.x * 256 + threadIdx.x) * 4;
    float4 f = *(const float4*)&w[idx];
    uint2 h, l;
    pack_trunc2(f.x, f.y, h.x, l.x);
    pack_trunc2(f.z, f.w, h.y, l.y);
    *(uint2*)&hi[m * WMAT + idx] = h;
    *(uint2*)&lo[m * WMAT + idx] = l;
}

// =============================================================================
// Tensor-core (HMMA) GEMM body: fp32 A convert-in-kernel (truncation split),
// bf16 B planes via cp.async. MODE 0: scatter bf16 hi/lo (scaled) to [b,h,n,d].
// MODE 1: fp32 row-major.
// =============================================================================
#define ASTRIDE 40
#define BSTRIDE 136
#define A_BYTES (128*ASTRIDE*2)
#define B_PLANE (32*BSTRIDE*2)
#define OFF_ALO A_BYTES
#define OFF_BHI (2*A_BYTES)
#define OFF_BLO (OFF_BHI + B_PLANE)
#define GBUF    (OFF_BHI + 2*B_PLANE)
#define GEMM_SMEM (2*GBUF)

template<int MODE>
__device__ __forceinline__ void gemm_body(
    const float* __restrict__ X,
    const __nv_bfloat16* __restrict__ Whi, const __nv_bfloat16* __restrict__ Wlo,
    const float* __restrict__ bias, float* __restrict__ out,
    __nv_bfloat16* __restrict__ ohi, __nv_bfloat16* __restrict__ olo,
    float oscale, char* smem)
{
    const uint32_t sb = smem_u32(smem);
    const int tid  = threadIdx.x;
    const int wid  = tid >> 5, lane = tid & 31;
    const int wm   = wid >> 2;
    const int wn   = wid & 3;
    const int n0   = blockIdx.x * 128;
    const int m0   = blockIdx.y * 128;

    float acc[4][4][4];
    #pragma unroll
    for (int i = 0; i < 4; i++)
        #pragma unroll
        for (int j = 0; j < 4; j++)
            #pragma unroll
            for (int k = 0; k < 4; k++) acc[i][j][k] = 0.f;

    float4 ra[4];

    auto gload = [&](int c) {
        const int k0 = c * 32;
        #pragma unroll
        for (int i = 0; i < 4; i++) {
            int idx = i * 256 + tid;
            int row = idx >> 3, col = (idx & 7) * 4;
            ra[i] = *(const float4*)&X[(size_t)(m0 + row) * 512 + k0 + col];
        }
    };
    auto bload = [&](int c, int buf) {
        const int k0 = c * 32;
        uint32_t dst = sb + buf * GBUF + OFF_BHI;
        const __nv_bfloat16* sh = Whi + (size_t)k0 * 512 + n0;
        const __nv_bfloat16* sl = Wlo + (size_t)k0 * 512 + n0;
        #pragma unroll
        for (int i = 0; i < 2; i++) {
            int idx = i * 256 + tid;
            int row = idx >> 4, col8 = (idx & 15) * 8;
            uint32_t d = dst + (uint32_t)(row * BSTRIDE + col8) * 2;
            cp16(d,           sh + row * 512 + col8);
            cp16(d + B_PLANE, sl + row * 512 + col8);
        }
    };
    auto cstore = [&](int buf) {
        char* bp = smem + buf * GBUF;
        #pragma unroll
        for (int i = 0; i < 4; i++) {
            int idx = i * 256 + tid;
            int row = idx >> 3, col = (idx & 7) * 4;
            uint2 hi, lo;
            pack_trunc2(ra[i].x, ra[i].y, hi.x, lo.x);
            pack_trunc2(ra[i].z, ra[i].w, hi.y, lo.y);
            uint32_t off = (uint32_t)(row * ASTRIDE + col) * 2;
            *(uint2*)(bp + off)           = hi;
            *(uint2*)(bp + OFF_ALO + off) = lo;
        }
    };

    const uint32_t aLane = (uint32_t)((wm * 64 + (lane & 15)) * ASTRIDE + (lane >> 4) * 8) * 2;
    const uint32_t bLane = (uint32_t)((lane & 15) * BSTRIDE + wn * 32 + (lane >> 4) * 8) * 2;

    auto compute = [&](int buf) {
        const uint32_t base = sb + buf * GBUF;
        #pragma unroll
        for (int ks = 0; ks < 2; ks++) {
            uint32_t ah[4][4], al[4][4], bh[2][4], bl[2][4];
            #pragma unroll
            for (int mt = 0; mt < 4; mt++) {
                uint32_t ad = base + aLane + (uint32_t)(mt * 16 * ASTRIDE + ks * 16) * 2;
                ldsm_x4(ah[mt], ad);
                ldsm_x4(al[mt], ad + OFF_ALO);
            }
            #pragma unroll
            for (int nt = 0; nt < 2; nt++) {
                uint32_t bd = base + OFF_BHI + bLane +
                              (uint32_t)(ks * 16 * BSTRIDE + nt * 16) * 2;
                ldsm_x4t(bh[nt], bd);
                ldsm_x4t(bl[nt], bd + B_PLANE);
            }
            #pragma unroll
            for (int mt = 0; mt < 4; mt++) {
                #pragma unroll
                for (int n8 = 0; n8 < 4; n8++) {
                    const int nt = n8 >> 1, hf = (n8 & 1) * 2;
                    float* c = acc[mt][n8];
                    mma_bf16(c, ah[mt], bh[nt][hf], bh[nt][hf + 1]);
                    mma_bf16(c, ah[mt], bl[nt][hf], bl[nt][hf + 1]);
                    mma_bf16(c, al[mt], bh[nt][hf], bh[nt][hf + 1]);
                }
            }
        }
    };

    gload(0);
    bload(0, 0);
    CP_COMMIT();
    cstore(0);
    CP_WAIT0();
    __syncthreads();
    for (int c = 0; c < 16; c++) {
        if (c < 15) {
            bload(c + 1, (c + 1) & 1);
            CP_COMMIT();
            gload(c + 1);
        }
        compute(c & 1);
        if (c < 15) {
            cstore((c + 1) & 1);
            CP_WAIT0();
            __syncthreads();
        }
    }

    const int gid = lane >> 2;
    const int cid = (lane & 3) * 2;
    #pragma unroll
    for (int mt = 0; mt < 4; mt++) {
        #pragma unroll
        for (int n8 = 0; n8 < 4; n8++) {
            int row = m0 + wm * 64 + mt * 16 + gid;
            int col = n0 + wn * 32 + n8 * 8 + cid;
            float b0 = __ldg(&bias[col]), b1 = __ldg(&bias[col + 1]);
            float2 v0 = make_float2(acc[mt][n8][0] + b0, acc[mt][n8][1] + b1);
            float2 v1 = make_float2(acc[mt][n8][2] + b0, acc[mt][n8][3] + b1);
            if (MODE == 0) {
                v0.x *= oscale; v0.y *= oscale;
                v1.x *= oscale; v1.y *= oscale;
                int h = col >> 6, d = col & 63;
                #pragma unroll
                for (int rr = 0; rr < 2; rr++) {
                    int r = row + rr * 8;
                    float2 v = rr ? v1 : v0;
                    int bi = r >> 10, ni = r & 1023;
                    size_t idx = (size_t)(((bi * NH + h) << 10) + ni) * 64 + d;
                    uint32_t hi, lo;
                    pack_trunc2(v.x, v.y, hi, lo);
                    *(uint32_t*)&ohi[idx] = hi;
                    *(uint32_t*)&olo[idx] = lo;
                }
            } else {
                *(float2*)&out[(size_t)row * 512 + col]       = v0;
                *(float2*)&out[(size_t)(row + 8) * 512 + col] = v1;
            }
        }
    }
}

__global__ __launch_bounds__(256, 2) void gemm_qkv(
    const float* xq, const float* xk, const float* xv,
    const __nv_bfloat16* whi, const __nv_bfloat16* wlo,
    const float* bq, const float* bk, const float* bv,
    __nv_bfloat16* qh, __nv_bfloat16* ql,
    __nv_bfloat16* kh, __nv_bfloat16* kl,
    __nv_bfloat16* vh, __nv_bfloat16* vl)
{
    extern __shared__ char smem[];
    const int z = blockIdx.z;
    const float* X = (z == 0) ? xq : (z == 1) ? xk : xv;
    const float* B = (z == 0) ? bq : (z == 1) ? bk : bv;
    __nv_bfloat16* oh = (z == 0) ? qh : (z == 1) ? kh : vh;
    __nv_bfloat16* ol = (z == 0) ? ql : (z == 1) ? kl : vl;
    float sc = (z == 0) ? EXC : 1.0f;
    gemm_body<0>(X, whi + (size_t)z * WMAT, wlo + (size_t)z * WMAT,
                 B, nullptr, oh, ol, sc, smem);
}

__global__ __launch_bounds__(256, 2) void gemm_out(
    const float* __restrict__ X,
    const __nv_bfloat16* __restrict__ whi, const __nv_bfloat16* __restrict__ wlo,
    const float* __restrict__ bias, float* __restrict__ out)
{
    extern __shared__ char smem[];
    gemm_body<1>(X, whi + (size_t)3 * WMAT, wlo + (size_t)3 * WMAT,
                 bias, out, nullptr, nullptr, 1.0f, smem);
}

// =============================================================================
// Register-resident fused attention. Q pre-scaled; QK correction chains merged
// (2 accumulator sets instead of 3); truncation packP.
// 512 threads / 16 warps, 32 q-rows/CTA, triple-buffered 16-chunk pipeline.
// =============================================================================
#define KVSTR   144
#define ATT_KVSZ 36864
#define ATT_LO   18432
#define ATT_Q    (3*ATT_KVSZ)
#define ATT_QLO  4608
#define ATT_W    (ATT_Q + 9216)
#define WSTR     132
#define ATT_WSZ  (32*WSTR*4)
#define ATT_PS   (ATT_W + 3*ATT_WSZ)
#define ATT_SMEM (ATT_PS + 1024)

__global__ __launch_bounds__(512, 1) void attn_tc(
    const __nv_bfloat16* __restrict__ qhi, const __nv_bfloat16* __restrict__ qlo,
    const __nv_bfloat16* __restrict__ khi, const __nv_bfloat16* __restrict__ klo,
    const __nv_bfloat16* __restrict__ vhi, const __nv_bfloat16* __restrict__ vlo,
    const float* __restrict__ gw, float* __restrict__ mn,
    float* __restrict__ attnout)
{
    extern __shared__ char smem[];
    const uint32_t sb = smem_u32(smem);
    float* psums = (float*)(smem + ATT_PS);

    const int tid = threadIdx.x, wid = tid >> 5, lane = tid & 31;
    const int wmq = wid >> 3;
    const int wq  = wid & 7;
    const int q0 = blockIdx.x * 32, hh = blockIdx.y, bb = blockIdx.z;
    const size_t bhBase = (size_t)(bb * NH + hh) * NSEQ;

    auto loadChunk = [&](const __nv_bfloat16* hi, const __nv_bfloat16* lo,
                         int kb, int buf) {
        uint32_t dst = sb + buf * ATT_KVSZ;
        const __nv_bfloat16* sh = hi + (bhBase + kb * 128) * 64;
        const __nv_bfloat16* sl = lo + (bhBase + kb * 128) * 64;
        #pragma unroll
        for (int i = 0; i < 2; i++) {
            int idx = i * 512 + tid;
            int row = idx >> 3, col = (idx & 7) * 8;
            uint32_t d = dst + row * KVSTR + col * 2;
            cp16(d,          sh + row * 64 + col);
            cp16(d + ATT_LO, sl + row * 64 + col);
        }
    };
    auto loadW = [&](int kb, int buf) {
        uint32_t dst = sb + ATT_W + buf * ATT_WSZ;
        const float* src = gw + ((bhBase + q0) << 10) + kb * 128;
        #pragma unroll
        for (int i = 0; i < 2; i++) {
            int idx = i * 512 + tid;
            int row = idx >> 5, col = (idx & 31) * 4;
            cp16(dst + (uint32_t)(row * WSTR + col) * 4,
                 src + ((size_t)row << 10) + col);
        }
    };

    loadChunk(khi, klo, 0, 0);
    loadW(0, 0);
    CP_COMMIT();
    loadChunk(khi, klo, 1, 1);
    loadW(1, 1);
    CP_COMMIT();

    {
        int pos = tid & 255;
        int row = pos >> 3, col = (pos & 7) * 8;
        size_t g = (bhBase + q0 + row) * 64 + col;
        if (tid < 256)
            *(uint4*)(smem + ATT_Q + row * KVSTR + col * 2)           = *(const uint4*)&qhi[g];
        else
            *(uint4*)(smem + ATT_Q + ATT_QLO + row * KVSTR + col * 2) = *(const uint4*)&qlo[g];
    }
    __syncthreads();

    uint32_t aQh[4][4], aQl[4][4];
    {
        const uint32_t qaddr = sb + ATT_Q +
            ((uint32_t)((wmq * 16 + (lane & 15)) * 72) + (lane >> 4) * 8) * 2;
        #pragma unroll
        for (int ks = 0; ks < 4; ks++) {
            ldsm_x4(aQh[ks], qaddr + ks * 32);
            ldsm_x4(aQl[ks], qaddr + ks * 32 + ATT_QLO);
        }
    }

    const int g   = lane >> 2;
    const int c2  = (lane & 3) * 2;
    const int rl0 = wmq * 16 + g;
    const size_t grow0 = (bhBase + q0 + rl0) << 10;

    // ========== QK^T (Q pre-scaled) + fused w*exp2(score) + running sums ======
    float s[8][8];
    float sum0 = 0.f, sum1 = 0.f;
    for (int kb = 0; kb < 8; kb++) {
        CP_WAIT1();
        __syncthreads();
        {
            int nc = kb + 2;
            if (nc < 8) {
                loadChunk(khi, klo, nc, nc % 3);
                loadW(nc, nc % 3);
            } else {
                loadChunk(vhi, vlo, nc - 8, nc % 3);
            }
            CP_COMMIT();
        }

        const uint32_t baddr = sb + (kb % 3) * ATT_KVSZ +
            ((uint32_t)((wq * 16 + (lane & 15)) * 72) + (lane >> 4) * 8) * 2;

        // main chain (hi*hi) + single merged correction chain (hi*lo + lo*hi)
        float t0h[4] = {0,0,0,0}, t0c[4] = {0,0,0,0};
        float t1h[4] = {0,0,0,0}, t1c[4] = {0,0,0,0};
        #pragma unroll
        for (int ks = 0; ks < 4; ks++) {
            uint32_t bh[4], bl[4];
            ldsm_x4(bh, baddr + ks * 32);
            ldsm_x4(bl, baddr + ks * 32 + ATT_LO);
            mma_bf16(t0h, aQh[ks], bh[0], bh[2]);
            mma_bf16(t0c, aQh[ks], bl[0], bl[2]);
            mma_bf16(t0c, aQl[ks], bh[0], bh[2]);
            mma_bf16(t1h, aQh[ks], bh[1], bh[3]);
            mma_bf16(t1c, aQh[ks], bl[1], bl[3]);
            mma_bf16(t1c, aQl[ks], bh[1], bh[3]);
        }

        const float* wsm = (const float*)(smem + ATT_W + (kb % 3) * ATT_WSZ);
        #pragma unroll
        for (int nt = 0; nt < 2; nt++) {
            int wcol = wq * 16 + nt * 8 + c2;
            float2 wa = *(const float2*)&wsm[rl0 * WSTR + wcol];
            float2 wb = *(const float2*)&wsm[(rl0 + 8) * WSTR + wcol];
            int j = nt * 4;
            float* th = nt ? t1h : t0h;
            float* tc = nt ? t1c : t0c;
            float e0 = fmaxf(wa.x, 1e-6f) * exp2f(th[0] + tc[0]);
            float e1 = fmaxf(wa.y, 1e-6f) * exp2f(th[1] + tc[1]);
            float e2 = fmaxf(wb.x, 1e-6f) * exp2f(th[2] + tc[2]);
            float e3 = fmaxf(wb.y, 1e-6f) * exp2f(th[3] + tc[3]);
            s[kb][j + 0] = e0; s[kb][j + 1] = e1;
            s[kb][j + 2] = e2; s[kb][j + 3] = e3;
            sum0 += e0 + e1;
            sum1 += e2 + e3;
        }
    }

    // ========== sum reduction (V0/V1 landing meanwhile) ==========
    sum0 += __shfl_xor_sync(0xffffffffu, sum0, 1);
    sum0 += __shfl_xor_sync(0xffffffffu, sum0, 2);
    sum1 += __shfl_xor_sync(0xffffffffu, sum1, 1);
    sum1 += __shfl_xor_sync(0xffffffffu, sum1, 2);
    if ((lane & 3) == 0) {
        psums[rl0 * 8 + wq]       = sum0;
        psums[(rl0 + 8) * 8 + wq] = sum1;
    }
    __syncthreads();
    float inv0, inv1;
    {
        float t0 = 0.f, t1 = 0.f;
        #pragma unroll
        for (int i = 0; i < 8; i++) {
            t0 += psums[rl0 * 8 + i];
            t1 += psums[(rl0 + 8) * 8 + i];
        }
        inv0 = 1.f / t0; inv1 = 1.f / t1;
    }

    // ========== P @ V with fused normalize/pack/mn-store ==========
    float* mrow0 = mn + grow0;
    float* mrow1 = mn + grow0 + (8 << 10);
    float accO[8][4];
    #pragma unroll
    for (int t = 0; t < 8; t++)
        #pragma unroll
        for (int j = 0; j < 4; j++) accO[t][j] = 0.f;

    for (int kb = 0; kb < 8; kb++) {
        const int c = kb + 8;
        CP_WAIT1();
        __syncthreads();
        {
            int nc = c + 2;
            if (nc < 16) loadChunk(vhi, vlo, nc - 8, nc % 3);
            CP_COMMIT();
        }

        #pragma unroll
        for (int nt = 0; nt < 2; nt++) {
            int col = kb * 128 + wq * 16 + nt * 8 + c2;
            int j = nt * 4;
            float p0 = s[kb][j + 0] * inv0;
            float p1 = s[kb][j + 1] * inv0;
            float p2 = s[kb][j + 2] * inv1;
            float p3 = s[kb][j + 3] * inv1;
            *(float2*)&mrow0[col] = make_float2(p0, p1);
            *(float2*)&mrow1[col] = make_float2(p2, p3);
            s[kb][j + 0] = __uint_as_float(packP(p0));
            s[kb][j + 1] = __uint_as_float(packP(p1));
            s[kb][j + 2] = __uint_as_float(packP(p2));
            s[kb][j + 3] = __uint_as_float(packP(p3));
        }

        uint32_t ah[4], al[4];
        {
            uint32_t w0 = __float_as_uint(s[kb][0]), w1 = __float_as_uint(s[kb][1]);
            uint32_t w2 = __float_as_uint(s[kb][2]), w3 = __float_as_uint(s[kb][3]);
            uint32_t w4 = __float_as_uint(s[kb][4]), w5 = __float_as_uint(s[kb][5]);
            uint32_t w6 = __float_as_uint(s[kb][6]), w7 = __float_as_uint(s[kb][7]);
            ah[0] = __byte_perm(w0, w1, 0x5410); al[0] = __byte_perm(w0, w1, 0x7632);
            ah[1] = __byte_perm(w2, w3, 0x5410); al[1] = __byte_perm(w2, w3, 0x7632);
            ah[2] = __byte_perm(w4, w5, 0x5410); al[2] = __byte_perm(w4, w5, 0x7632);
            ah[3] = __byte_perm(w6, w7, 0x5410); al[3] = __byte_perm(w6, w7, 0x7632);
        }

        const uint32_t vbase = sb + (c % 3) * ATT_KVSZ;
        #pragma unroll
        for (int ng = 0; ng < 4; ng++) {
            uint32_t vaddr = vbase +
                ((uint32_t)((wq * 16 + (lane & 15)) * 72) +
                 ng * 16 + (lane >> 4) * 8) * 2;
            uint32_t bh[4], bl[4];
            ldsm_x4t(bh, vaddr);
            ldsm_x4t(bl, vaddr + ATT_LO);
            float* c0 = accO[ng * 2];
            float* c1 = accO[ng * 2 + 1];
            mma_bf16(c0, ah, bh[0], bh[1]);
            mma_bf16(c0, ah, bl[0], bl[1]);
            mma_bf16(c0, al, bh[0], bh[1]);
            mma_bf16(c1, ah, bh[2], bh[3]);
            mma_bf16(c1, ah, bl[2], bl[3]);
            mma_bf16(c1, al, bh[2], bh[3]);
        }
    }
    __syncthreads();

    float* red = (float*)smem;
    {
        float* slab = red + wid * 1024;
        #pragma unroll
        for (int t = 0; t < 8; t++) {
            int col = (t >> 1) * 16 + (t & 1) * 8 + c2;
            *(float2*)&slab[g * 64 + col]       = make_float2(accO[t][0], accO[t][1]);
            *(float2*)&slab[(g + 8) * 64 + col] = make_float2(accO[t][2], accO[t][3]);
        }
    }
    __syncthreads();
    {
        int row = tid >> 4;
        int c4  = (tid & 15) * 4;
        int h   = row >> 4, rl = row & 15;
        float4 v = make_float4(0.f, 0.f, 0.f, 0.f);
        #pragma unroll
        for (int w2 = 0; w2 < 8; w2++) {
            float4 p = *(float4*)&red[(h * 8 + w2) * 1024 + rl * 64 + c4];
            v.x += p.x; v.y += p.y; v.z += p.z; v.w += p.w;
        }
        float* dst = attnout + (size_t)(bb * NSEQ + q0 + row) * 512 + hh * 64 + c4;
        *(float4*)dst = v;
    }
}

// =============================================================================
extern "C" void kernel_launch(void* const* d_in, const int* in_sizes, int n_in,
                              void* d_out, int out_size)
{
    const float* queries = (const float*)d_in[0];
    const float* keys    = (const float*)d_in[1];
    const float* values  = (const float*)d_in[2];
    const float* relw    = (const float*)d_in[3];
    const float* Wq = (const float*)d_in[4];
    const float* bq = (const float*)d_in[5];
    const float* Wk = (const float*)d_in[6];
    const float* bk = (const float*)d_in[7];
    const float* Wv = (const float*)d_in[8];
    const float* bv = (const float*)d_in[9];
    const float* Wo = (const float*)d_in[10];
    const float* bo = (const float*)d_in[11];

    float* out_main = (float*)d_out;
    float* out_mn   = (float*)d_out + (size_t)BATCH * NSEQ * DM;

    __nv_bfloat16 *qhi, *qlo, *khi, *klo, *vhi, *vlo, *whi, *wlo;
    float* gattn;
    cudaGetSymbolAddress((void**)&qhi, g_qhi);
    cudaGetSymbolAddress((void**)&qlo, g_qlo);
    cudaGetSymbolAddress((void**)&khi, g_khi);
    cudaGetSymbolAddress((void**)&klo, g_klo);
    cudaGetSymbolAddress((void**)&vhi, g_vhi);
    cudaGetSymbolAddress((void**)&vlo, g_vlo);
    cudaGetSymbolAddress((void**)&whi, g_whi);
    cudaGetSymbolAddress((void**)&wlo, g_wlo);
    cudaGetSymbolAddress((void**)&gattn, g_attn);

    cudaFuncSetAttribute(gemm_qkv, cudaFuncAttributeMaxDynamicSharedMemorySize, GEMM_SMEM);
    cudaFuncSetAttribute(gemm_out, cudaFuncAttributeMaxDynamicSharedMemorySize, GEMM_SMEM);
    cudaFuncSetAttribute(attn_tc, cudaFuncAttributeMaxDynamicSharedMemorySize, ATT_SMEM);

    conv_w<<<dim3(256, 4), 256>>>(Wq, Wk, Wv, Wo, whi, wlo);

    gemm_qkv<<<dim3(4, 128, 3), 256, GEMM_SMEM>>>(
        queries, keys, values, whi, wlo, bq, bk, bv,
        qhi, qlo, khi, klo, vhi, vlo);

    attn_tc<<<dim3(32, NH, BATCH), 512, ATT_SMEM>>>(
        qhi, qlo, khi, klo, vhi, vlo, relw, out_mn, gattn);

    gemm_out<<<dim3(4, 128), 256, GEMM_SMEM>>>(gattn, whi, wlo, bo, out_main);
}

// round 17
// speedup vs baseline: 1.0196x; 1.0196x over previous
#include <cuda_runtime.h>
#include <cuda_bf16.h>
#include <cstdint>
#include <math.h>

#define BATCH 16
#define NSEQ  1024
#define NH    8
#define HD    64
#define DM    512

// ---------------- scratch (static device arrays; no allocation) ----------------
#define QKV_ELEMS (BATCH*NH*NSEQ*HD)
__device__ __nv_bfloat16 g_qhi[QKV_ELEMS];
__device__ __nv_bfloat16 g_qlo[QKV_ELEMS];
__device__ __nv_bfloat16 g_khi[QKV_ELEMS];
__device__ __nv_bfloat16 g_klo[QKV_ELEMS];
__device__ __nv_bfloat16 g_vhi[QKV_ELEMS];
__device__ __nv_bfloat16 g_vlo[QKV_ELEMS];
__device__ float g_attn[BATCH*NSEQ*DM];
#define WMAT (512*512)
__device__ __nv_bfloat16 g_whi[4*WMAT];   // Wq, Wk, Wv, Wo hi planes
__device__ __nv_bfloat16 g_wlo[4*WMAT];

// =============================================================================
// helpers
// =============================================================================
__device__ __forceinline__ uint32_t smem_u32(const void* p) {
    uint32_t a;
    asm("{ .reg .u64 t; cvta.to.shared.u64 t, %1; cvt.u32.u64 %0, t; }"
        : "=r"(a) : "l"(p));
    return a;
}
__device__ __forceinline__ void ldsm_x4(uint32_t* r, uint32_t addr) {
    asm volatile("ldmatrix.sync.aligned.m8n8.x4.shared.b16 {%0,%1,%2,%3}, [%4];"
        : "=r"(r[0]), "=r"(r[1]), "=r"(r[2]), "=r"(r[3]) : "r"(addr));
}
__device__ __forceinline__ void ldsm_x4t(uint32_t* r, uint32_t addr) {
    asm volatile("ldmatrix.sync.aligned.m8n8.x4.trans.shared.b16 {%0,%1,%2,%3}, [%4];"
        : "=r"(r[0]), "=r"(r[1]), "=r"(r[2]), "=r"(r[3]) : "r"(addr));
}
__device__ __forceinline__ void mma_bf16(float* c, const uint32_t* a,
                                         uint32_t b0, uint32_t b1) {
    asm volatile(
        "mma.sync.aligned.m16n8k16.row.col.f32.bf16.bf16.f32 "
        "{%0,%1,%2,%3}, {%4,%5,%6,%7}, {%8,%9}, {%0,%1,%2,%3};"
        : "+f"(c[0]), "+f"(c[1]), "+f"(c[2]), "+f"(c[3])
        : "r"(a[0]), "r"(a[1]), "r"(a[2]), "r"(a[3]), "r"(b0), "r"(b1));
}
__device__ __forceinline__ void cp16(uint32_t dst, const void* src) {
    asm volatile("cp.async.cg.shared.global [%0], [%1], 16;" :: "r"(dst), "l"(src));
}
#define CP_COMMIT() asm volatile("cp.async.commit_group;" ::: "memory")
#define CP_WAIT0()  asm volatile("cp.async.wait_group 0;" ::: "memory")
#define CP_WAIT1()  asm volatile("cp.async.wait_group 1;" ::: "memory")

__device__ __forceinline__ uint32_t pack_bf16_res(float a, float b, float& ra, float& rb) {
    __nv_bfloat16 ha = __float2bfloat16(a), hb = __float2bfloat16(b);
    ra = a - __bfloat162float(ha);
    rb = b - __bfloat162float(hb);
    __nv_bfloat162 p(ha, hb);
    return *reinterpret_cast<uint32_t*>(&p);
}
__device__ __forceinline__ uint32_t pack_bf16(float a, float b) {
    __nv_bfloat162 p(__float2bfloat16(a), __float2bfloat16(b));
    return *reinterpret_cast<uint32_t*>(&p);
}
// word: low16 = bf16 hi(p), high16 = bf16 lo-residual(p)
__device__ __forceinline__ uint32_t packP(float p) {
    __nv_bfloat16 hi = __float2bfloat16(p);
    __nv_bfloat16 lo = __float2bfloat16(p - __bfloat162float(hi));
    uint16_t hb = *reinterpret_cast<uint16_t*>(&hi);
    uint16_t lb = *reinterpret_cast<uint16_t*>(&lo);
    return (uint32_t)hb | ((uint32_t)lb << 16);
}

// =============================================================================
// Weight pre-conversion: fp32 [512,512] -> bf16 hi/lo planes (once, all 4 mats)
// =============================================================================
__global__ __launch_bounds__(256) void conv_w(
    const float* w0, const float* w1, const float* w2, const float* w3,
    __nv_bfloat16* hi, __nv_bfloat16* lo)
{
    const int m = blockIdx.y;
    const float* w = (m == 0) ? w0 : (m == 1) ? w1 : (m == 2) ? w2 : w3;
    int idx = (blockIdx.x * 256 + threadIdx.x) * 4;
    float4 f = *(const float4*)&w[idx];
    float r0, r1, r2, r3;
    uint2 h, l;
    h.x = pack_bf16_res(f.x, f.y, r0, r1);
    h.y = pack_bf16_res(f.z, f.w, r2, r3);
    l.x = pack_bf16(r0, r1);
    l.y = pack_bf16(r2, r3);
    *(uint2*)&hi[m * WMAT + idx] = h;
    *(uint2*)&lo[m * WMAT + idx] = l;
}

// =============================================================================
// Tensor-core (HMMA) GEMM body: fp32 A convert-in-kernel, bf16 B planes via
// cp.async. MODE 0: scatter bf16 hi/lo to [b,h,n,d]. MODE 1: fp32 row-major.
// =============================================================================
#define ASTRIDE 40
#define BSTRIDE 136
#define A_BYTES (128*ASTRIDE*2)        // 10240
#define B_PLANE (32*BSTRIDE*2)         // 8704
#define OFF_ALO A_BYTES
#define OFF_BHI (2*A_BYTES)            // 20480
#define OFF_BLO (OFF_BHI + B_PLANE)    // 29184
#define GBUF    (OFF_BHI + 2*B_PLANE)  // 37888
#define GEMM_SMEM (2*GBUF)             // 75776

template<int MODE>
__device__ __forceinline__ void gemm_body(
    const float* __restrict__ X,
    const __nv_bfloat16* __restrict__ Whi, const __nv_bfloat16* __restrict__ Wlo,
    const float* __restrict__ bias, float* __restrict__ out,
    __nv_bfloat16* __restrict__ ohi, __nv_bfloat16* __restrict__ olo,
    char* smem)
{
    const uint32_t sb = smem_u32(smem);
    const int tid  = threadIdx.x;
    const int wid  = tid >> 5, lane = tid & 31;
    const int wm   = wid >> 2;
    const int wn   = wid & 3;
    const int n0   = blockIdx.x * 128;
    const int m0   = blockIdx.y * 128;

    float acc[4][4][4];
    #pragma unroll
    for (int i = 0; i < 4; i++)
        #pragma unroll
        for (int j = 0; j < 4; j++)
            #pragma unroll
            for (int k = 0; k < 4; k++) acc[i][j][k] = 0.f;

    float4 ra[4];

    auto gload = [&](int c) {
        const int k0 = c * 32;
        #pragma unroll
        for (int i = 0; i < 4; i++) {
            int idx = i * 256 + tid;
            int row = idx >> 3, col = (idx & 7) * 4;
            ra[i] = *(const float4*)&X[(size_t)(m0 + row) * 512 + k0 + col];
        }
    };
    auto bload = [&](int c, int buf) {
        const int k0 = c * 32;
        uint32_t dst = sb + buf * GBUF + OFF_BHI;
        const __nv_bfloat16* sh = Whi + (size_t)k0 * 512 + n0;
        const __nv_bfloat16* sl = Wlo + (size_t)k0 * 512 + n0;
        #pragma unroll
        for (int i = 0; i < 2; i++) {
            int idx = i * 256 + tid;
            int row = idx >> 4, col8 = (idx & 15) * 8;
            uint32_t d = dst + (uint32_t)(row * BSTRIDE + col8) * 2;
            cp16(d,           sh + row * 512 + col8);
            cp16(d + B_PLANE, sl + row * 512 + col8);
        }
    };
    auto cstore = [&](int buf) {
        char* bp = smem + buf * GBUF;
        #pragma unroll
        for (int i = 0; i < 4; i++) {
            int idx = i * 256 + tid;
            int row = idx >> 3, col = (idx & 7) * 4;
            float r0, r1, r2, r3;
            uint2 hi, lo;
            hi.x = pack_bf16_res(ra[i].x, ra[i].y, r0, r1);
            hi.y = pack_bf16_res(ra[i].z, ra[i].w, r2, r3);
            lo.x = pack_bf16(r0, r1);
            lo.y = pack_bf16(r2, r3);
            uint32_t off = (uint32_t)(row * ASTRIDE + col) * 2;
            *(uint2*)(bp + off)           = hi;
            *(uint2*)(bp + OFF_ALO + off) = lo;
        }
    };

    const uint32_t aLane = (uint32_t)((wm * 64 + (lane & 15)) * ASTRIDE + (lane >> 4) * 8) * 2;
    const uint32_t bLane = (uint32_t)((lane & 15) * BSTRIDE + wn * 32 + (lane >> 4) * 8) * 2;

    auto compute = [&](int buf) {
        const uint32_t base = sb + buf * GBUF;
        #pragma unroll
        for (int ks = 0; ks < 2; ks++) {
            uint32_t ah[4][4], al[4][4], bh[2][4], bl[2][4];
            #pragma unroll
            for (int mt = 0; mt < 4; mt++) {
                uint32_t ad = base + aLane + (uint32_t)(mt * 16 * ASTRIDE + ks * 16) * 2;
                ldsm_x4(ah[mt], ad);
                ldsm_x4(al[mt], ad + OFF_ALO);
            }
            #pragma unroll
            for (int nt = 0; nt < 2; nt++) {
                uint32_t bd = base + OFF_BHI + bLane +
                              (uint32_t)(ks * 16 * BSTRIDE + nt * 16) * 2;
                ldsm_x4t(bh[nt], bd);
                ldsm_x4t(bl[nt], bd + B_PLANE);
            }
            #pragma unroll
            for (int mt = 0; mt < 4; mt++) {
                #pragma unroll
                for (int n8 = 0; n8 < 4; n8++) {
                    const int nt = n8 >> 1, hf = (n8 & 1) * 2;
                    float* c = acc[mt][n8];
                    mma_bf16(c, ah[mt], bh[nt][hf], bh[nt][hf + 1]);
                    mma_bf16(c, ah[mt], bl[nt][hf], bl[nt][hf + 1]);
                    mma_bf16(c, al[mt], bh[nt][hf], bh[nt][hf + 1]);
                }
            }
        }
    };

    gload(0);
    bload(0, 0);
    CP_COMMIT();
    cstore(0);
    CP_WAIT0();
    __syncthreads();
    for (int c = 0; c < 16; c++) {
        if (c < 15) {
            bload(c + 1, (c + 1) & 1);
            CP_COMMIT();
            gload(c + 1);
        }
        compute(c & 1);
        if (c < 15) {
            cstore((c + 1) & 1);
            CP_WAIT0();
            __syncthreads();
        }
    }

    const int gid = lane >> 2;
    const int cid = (lane & 3) * 2;
    #pragma unroll
    for (int mt = 0; mt < 4; mt++) {
        #pragma unroll
        for (int n8 = 0; n8 < 4; n8++) {
            int row = m0 + wm * 64 + mt * 16 + gid;
            int col = n0 + wn * 32 + n8 * 8 + cid;
            float b0 = __ldg(&bias[col]), b1 = __ldg(&bias[col + 1]);
            float2 v0 = make_float2(acc[mt][n8][0] + b0, acc[mt][n8][1] + b1);
            float2 v1 = make_float2(acc[mt][n8][2] + b0, acc[mt][n8][3] + b1);
            if (MODE == 0) {
                int h = col >> 6, d = col & 63;
                #pragma unroll
                for (int rr = 0; rr < 2; rr++) {
                    int r = row + rr * 8;
                    float2 v = rr ? v1 : v0;
                    int bi = r >> 10, ni = r & 1023;
                    size_t idx = (size_t)(((bi * NH + h) << 10) + ni) * 64 + d;
                    float e0, e1;
                    uint32_t hi = pack_bf16_res(v.x, v.y, e0, e1);
                    uint32_t lo = pack_bf16(e0, e1);
                    *(uint32_t*)&ohi[idx] = hi;
                    *(uint32_t*)&olo[idx] = lo;
                }
            } else {
                *(float2*)&out[(size_t)row * 512 + col]       = v0;
                *(float2*)&out[(size_t)(row + 8) * 512 + col] = v1;
            }
        }
    }
}

// fused QKV projection: blockIdx.z selects (X, W planes, bias, dst)
__global__ __launch_bounds__(256, 2) void gemm_qkv(
    const float* xq, const float* xk, const float* xv,
    const __nv_bfloat16* whi, const __nv_bfloat16* wlo,
    const float* bq, const float* bk, const float* bv,
    __nv_bfloat16* qh, __nv_bfloat16* ql,
    __nv_bfloat16* kh, __nv_bfloat16* kl,
    __nv_bfloat16* vh, __nv_bfloat16* vl)
{
    extern __shared__ char smem[];
    const int z = blockIdx.z;
    const float* X = (z == 0) ? xq : (z == 1) ? xk : xv;
    const float* B = (z == 0) ? bq : (z == 1) ? bk : bv;
    __nv_bfloat16* oh = (z == 0) ? qh : (z == 1) ? kh : vh;
    __nv_bfloat16* ol = (z == 0) ? ql : (z == 1) ? kl : vl;
    gemm_body<0>(X, whi + (size_t)z * WMAT, wlo + (size_t)z * WMAT,
                 B, nullptr, oh, ol, smem);
}

__global__ __launch_bounds__(256, 2) void gemm_out(
    const float* __restrict__ X,
    const __nv_bfloat16* __restrict__ whi, const __nv_bfloat16* __restrict__ wlo,
    const float* __restrict__ bias, float* __restrict__ out)
{
    extern __shared__ char smem[];
    gemm_body<1>(X, whi + (size_t)3 * WMAT, wlo + (size_t)3 * WMAT,
                 bias, out, nullptr, nullptr, smem);
}

// =============================================================================
// Register-resident fused attention (R11 — best measured).
// 512 threads / 16 warps, 32 q-rows/CTA, triple-buffered 16-chunk pipeline,
// log-free softmax: e = max(w,1e-6) * exp2(score * 0.125*log2(e)).
// =============================================================================
#define KVSTR   144
#define ATT_KVSZ 36864
#define ATT_LO   18432
#define ATT_Q    (3*ATT_KVSZ)
#define ATT_QLO  4608
#define ATT_W    (ATT_Q + 9216)
#define WSTR     132
#define ATT_WSZ  (32*WSTR*4)
#define ATT_PS   (ATT_W + 3*ATT_WSZ)
#define ATT_SMEM (ATT_PS + 1024)

__global__ __launch_bounds__(512, 1) void attn_tc(
    const __nv_bfloat16* __restrict__ qhi, const __nv_bfloat16* __restrict__ qlo,
    const __nv_bfloat16* __restrict__ khi, const __nv_bfloat16* __restrict__ klo,
    const __nv_bfloat16* __restrict__ vhi, const __nv_bfloat16* __restrict__ vlo,
    const float* __restrict__ gw, float* __restrict__ mn,
    float* __restrict__ attnout)
{
    extern __shared__ char smem[];
    const uint32_t sb = smem_u32(smem);
    float* psums = (float*)(smem + ATT_PS);

    const int tid = threadIdx.x, wid = tid >> 5, lane = tid & 31;
    const int wmq = wid >> 3;
    const int wq  = wid & 7;
    const int q0 = blockIdx.x * 32, hh = blockIdx.y, bb = blockIdx.z;
    const size_t bhBase = (size_t)(bb * NH + hh) * NSEQ;
    const float EXC = 0.18033688011112042f;   // 0.125 * log2(e)

    auto loadChunk = [&](const __nv_bfloat16* hi, const __nv_bfloat16* lo,
                         int kb, int buf) {
        uint32_t dst = sb + buf * ATT_KVSZ;
        const __nv_bfloat16* sh = hi + (bhBase + kb * 128) * 64;
        const __nv_bfloat16* sl = lo + (bhBase + kb * 128) * 64;
        #pragma unroll
        for (int i = 0; i < 2; i++) {
            int idx = i * 512 + tid;
            int row = idx >> 3, col = (idx & 7) * 8;
            uint32_t d = dst + row * KVSTR + col * 2;
            cp16(d,          sh + row * 64 + col);
            cp16(d + ATT_LO, sl + row * 64 + col);
        }
    };
    auto loadW = [&](int kb, int buf) {
        uint32_t dst = sb + ATT_W + buf * ATT_WSZ;
        const float* src = gw + ((bhBase + q0) << 10) + kb * 128;
        #pragma unroll
        for (int i = 0; i < 2; i++) {
            int idx = i * 512 + tid;
            int row = idx >> 5, col = (idx & 31) * 4;
            cp16(dst + (uint32_t)(row * WSTR + col) * 4,
                 src + ((size_t)row << 10) + col);
        }
    };

    loadChunk(khi, klo, 0, 0);
    loadW(0, 0);
    CP_COMMIT();
    loadChunk(khi, klo, 1, 1);
    loadW(1, 1);
    CP_COMMIT();

    {
        int pos = tid & 255;
        int row = pos >> 3, col = (pos & 7) * 8;
        size_t g = (bhBase + q0 + row) * 64 + col;
        if (tid < 256)
            *(uint4*)(smem + ATT_Q + row * KVSTR + col * 2)           = *(const uint4*)&qhi[g];
        else
            *(uint4*)(smem + ATT_Q + ATT_QLO + row * KVSTR + col * 2) = *(const uint4*)&qlo[g];
    }
    __syncthreads();

    uint32_t aQh[4][4], aQl[4][4];
    {
        const uint32_t qaddr = sb + ATT_Q +
            ((uint32_t)((wmq * 16 + (lane & 15)) * 72) + (lane >> 4) * 8) * 2;
        #pragma unroll
        for (int ks = 0; ks < 4; ks++) {
            ldsm_x4(aQh[ks], qaddr + ks * 32);
            ldsm_x4(aQl[ks], qaddr + ks * 32 + ATT_QLO);
        }
    }

    const int g   = lane >> 2;
    const int c2  = (lane & 3) * 2;
    const int rl0 = wmq * 16 + g;
    const size_t grow0 = (bhBase + q0 + rl0) << 10;

    // ========== QK^T + fused w*exp(score/8) + running sums ==========
    float s[8][8];
    float sum0 = 0.f, sum1 = 0.f;
    for (int kb = 0; kb < 8; kb++) {
        CP_WAIT1();
        __syncthreads();
        {
            int nc = kb + 2;
            if (nc < 8) {
                loadChunk(khi, klo, nc, nc % 3);
                loadW(nc, nc % 3);
            } else {
                loadChunk(vhi, vlo, nc - 8, nc % 3);
            }
            CP_COMMIT();
        }

        const uint32_t baddr = sb + (kb % 3) * ATT_KVSZ +
            ((uint32_t)((wq * 16 + (lane & 15)) * 72) + (lane >> 4) * 8) * 2;

        float t0h[4] = {0,0,0,0}, t0l[4] = {0,0,0,0}, t0m[4] = {0,0,0,0};
        float t1h[4] = {0,0,0,0}, t1l[4] = {0,0,0,0}, t1m[4] = {0,0,0,0};
        #pragma unroll
        for (int ks = 0; ks < 4; ks++) {
            uint32_t bh[4], bl[4];
            ldsm_x4(bh, baddr + ks * 32);
            ldsm_x4(bl, baddr + ks * 32 + ATT_LO);
            mma_bf16(t0h, aQh[ks], bh[0], bh[2]);
            mma_bf16(t0l, aQh[ks], bl[0], bl[2]);
            mma_bf16(t0m, aQl[ks], bh[0], bh[2]);
            mma_bf16(t1h, aQh[ks], bh[1], bh[3]);
            mma_bf16(t1l, aQh[ks], bl[1], bl[3]);
            mma_bf16(t1m, aQl[ks], bh[1], bh[3]);
        }

        const float* wsm = (const float*)(smem + ATT_W + (kb % 3) * ATT_WSZ);
        #pragma unroll
        for (int nt = 0; nt < 2; nt++) {
            int wcol = wq * 16 + nt * 8 + c2;
            float2 wa = *(const float2*)&wsm[rl0 * WSTR + wcol];
            float2 wb = *(const float2*)&wsm[(rl0 + 8) * WSTR + wcol];
            int j = nt * 4;
            float* ta = nt ? t1h : t0h;
            float* tb = nt ? t1l : t0l;
            float* tc = nt ? t1m : t0m;
            float e0 = fmaxf(wa.x, 1e-6f) * exp2f((ta[0] + tb[0] + tc[0]) * EXC);
            float e1 = fmaxf(wa.y, 1e-6f) * exp2f((ta[1] + tb[1] + tc[1]) * EXC);
            float e2 = fmaxf(wb.x, 1e-6f) * exp2f((ta[2] + tb[2] + tc[2]) * EXC);
            float e3 = fmaxf(wb.y, 1e-6f) * exp2f((ta[3] + tb[3] + tc[3]) * EXC);
            s[kb][j + 0] = e0; s[kb][j + 1] = e1;
            s[kb][j + 2] = e2; s[kb][j + 3] = e3;
            sum0 += e0 + e1;
            sum1 += e2 + e3;
        }
    }

    // ========== sum reduction (V0/V1 landing meanwhile) ==========
    sum0 += __shfl_xor_sync(0xffffffffu, sum0, 1);
    sum0 += __shfl_xor_sync(0xffffffffu, sum0, 2);
    sum1 += __shfl_xor_sync(0xffffffffu, sum1, 1);
    sum1 += __shfl_xor_sync(0xffffffffu, sum1, 2);
    if ((lane & 3) == 0) {
        psums[rl0 * 8 + wq]       = sum0;
        psums[(rl0 + 8) * 8 + wq] = sum1;
    }
    __syncthreads();
    float inv0, inv1;
    {
        float t0 = 0.f, t1 = 0.f;
        #pragma unroll
        for (int i = 0; i < 8; i++) {
            t0 += psums[rl0 * 8 + i];
            t1 += psums[(rl0 + 8) * 8 + i];
        }
        inv0 = 1.f / t0; inv1 = 1.f / t1;
    }

    // ========== P @ V with fused normalize/pack/mn-store ==========
    float* mrow0 = mn + grow0;
    float* mrow1 = mn + grow0 + (8 << 10);
    float accO[8][4];
    #pragma unroll
    for (int t = 0; t < 8; t++)
        #pragma unroll
        for (int j = 0; j < 4; j++) accO[t][j] = 0.f;

    for (int kb = 0; kb < 8; kb++) {
        const int c = kb + 8;
        CP_WAIT1();
        __syncthreads();
        {
            int nc = c + 2;
            if (nc < 16) loadChunk(vhi, vlo, nc - 8, nc % 3);
            CP_COMMIT();
        }

        #pragma unroll
        for (int nt = 0; nt < 2; nt++) {
            int col = kb * 128 + wq * 16 + nt * 8 + c2;
            int j = nt * 4;
            float p0 = s[kb][j + 0] * inv0;
            float p1 = s[kb][j + 1] * inv0;
            float p2 = s[kb][j + 2] * inv1;
            float p3 = s[kb][j + 3] * inv1;
            *(float2*)&mrow0[col] = make_float2(p0, p1);
            *(float2*)&mrow1[col] = make_float2(p2, p3);
            s[kb][j + 0] = __uint_as_float(packP(p0));
            s[kb][j + 1] = __uint_as_float(packP(p1));
            s[kb][j + 2] = __uint_as_float(packP(p2));
            s[kb][j + 3] = __uint_as_float(packP(p3));
        }

        uint32_t ah[4], al[4];
        {
            uint32_t w0 = __float_as_uint(s[kb][0]), w1 = __float_as_uint(s[kb][1]);
            uint32_t w2 = __float_as_uint(s[kb][2]), w3 = __float_as_uint(s[kb][3]);
            uint32_t w4 = __float_as_uint(s[kb][4]), w5 = __float_as_uint(s[kb][5]);
            uint32_t w6 = __float_as_uint(s[kb][6]), w7 = __float_as_uint(s[kb][7]);
            ah[0] = __byte_perm(w0, w1, 0x5410); al[0] = __byte_perm(w0, w1, 0x7632);
            ah[1] = __byte_perm(w2, w3, 0x5410); al[1] = __byte_perm(w2, w3, 0x7632);
            ah[2] = __byte_perm(w4, w5, 0x5410); al[2] = __byte_perm(w4, w5, 0x7632);
            ah[3] = __byte_perm(w6, w7, 0x5410); al[3] = __byte_perm(w6, w7, 0x7632);
        }

        const uint32_t vbase = sb + (c % 3) * ATT_KVSZ;
        #pragma unroll
        for (int ng = 0; ng < 4; ng++) {
            uint32_t vaddr = vbase +
                ((uint32_t)((wq * 16 + (lane & 15)) * 72) +
                 ng * 16 + (lane >> 4) * 8) * 2;
            uint32_t bh[4], bl[4];
            ldsm_x4t(bh, vaddr);
            ldsm_x4t(bl, vaddr + ATT_LO);
            float* c0 = accO[ng * 2];
            float* c1 = accO[ng * 2 + 1];
            mma_bf16(c0, ah, bh[0], bh[1]);
            mma_bf16(c0, ah, bl[0], bl[1]);
            mma_bf16(c0, al, bh[0], bh[1]);
            mma_bf16(c1, ah, bh[2], bh[3]);
            mma_bf16(c1, ah, bl[2], bl[3]);
            mma_bf16(c1, al, bh[2], bh[3]);
        }
    }
    __syncthreads();

    float* red = (float*)smem;
    {
        float* slab = red + wid * 1024;
        #pragma unroll
        for (int t = 0; t < 8; t++) {
            int col = (t >> 1) * 16 + (t & 1) * 8 + c2;
            *(float2*)&slab[g * 64 + col]       = make_float2(accO[t][0], accO[t][1]);
            *(float2*)&slab[(g + 8) * 64 + col] = make_float2(accO[t][2], accO[t][3]);
        }
    }
    __syncthreads();
    {
        int row = tid >> 4;
        int c4  = (tid & 15) * 4;
        int h   = row >> 4, rl = row & 15;
        float4 v = make_float4(0.f, 0.f, 0.f, 0.f);
        #pragma unroll
        for (int w2 = 0; w2 < 8; w2++) {
            float4 p = *(float4*)&red[(h * 8 + w2) * 1024 + rl * 64 + c4];
            v.x += p.x; v.y += p.y; v.z += p.z; v.w += p.w;
        }
        float* dst = attnout + (size_t)(bb * NSEQ + q0 + row) * 512 + hh * 64 + c4;
        *(float4*)dst = v;
    }
}

// =============================================================================
extern "C" void kernel_launch(void* const* d_in, const int* in_sizes, int n_in,
                              void* d_out, int out_size)
{
    const float* queries = (const float*)d_in[0];
    const float* keys    = (const float*)d_in[1];
    const float* values  = (const float*)d_in[2];
    const float* relw    = (const float*)d_in[3];
    const float* Wq = (const float*)d_in[4];
    const float* bq = (const float*)d_in[5];
    const float* Wk = (const float*)d_in[6];
    const float* bk = (const float*)d_in[7];
    const float* Wv = (const float*)d_in[8];
    const float* bv = (const float*)d_in[9];
    const float* Wo = (const float*)d_in[10];
    const float* bo = (const float*)d_in[11];

    float* out_main = (float*)d_out;
    float* out_mn   = (float*)d_out + (size_t)BATCH * NSEQ * DM;

    __nv_bfloat16 *qhi, *qlo, *khi, *klo, *vhi, *vlo, *whi, *wlo;
    float* gattn;
    cudaGetSymbolAddress((void**)&qhi, g_qhi);
    cudaGetSymbolAddress((void**)&qlo, g_qlo);
    cudaGetSymbolAddress((void**)&khi, g_khi);
    cudaGetSymbolAddress((void**)&klo, g_klo);
    cudaGetSymbolAddress((void**)&vhi, g_vhi);
    cudaGetSymbolAddress((void**)&vlo, g_vlo);
    cudaGetSymbolAddress((void**)&whi, g_whi);
    cudaGetSymbolAddress((void**)&wlo, g_wlo);
    cudaGetSymbolAddress((void**)&gattn, g_attn);

    cudaFuncSetAttribute(gemm_qkv, cudaFuncAttributeMaxDynamicSharedMemorySize, GEMM_SMEM);
    cudaFuncSetAttribute(gemm_out, cudaFuncAttributeMaxDynamicSharedMemorySize, GEMM_SMEM);
    cudaFuncSetAttribute(attn_tc, cudaFuncAttributeMaxDynamicSharedMemorySize, ATT_SMEM);

    conv_w<<<dim3(256, 4), 256>>>(Wq, Wk, Wv, Wo, whi, wlo);

    gemm_qkv<<<dim3(4, 128, 3), 256, GEMM_SMEM>>>(
        queries, keys, values, whi, wlo, bq, bk, bv,
        qhi, qlo, khi, klo, vhi, vlo);

    attn_tc<<<dim3(32, NH, BATCH), 512, ATT_SMEM>>>(
        qhi, qlo, khi, klo, vhi, vlo, relw, out_mn, gattn);

    gemm_out<<<dim3(4, 128), 256, GEMM_SMEM>>>(gattn, whi, wlo, bo, out_main);
}